// round 13
// baseline (speedup 1.0000x reference)
#include <cuda_runtime.h>
#include <cuda_bf16.h>
#include <cuda_fp16.h>
#include <math.h>
#include <stdint.h>

// Problem constants: B=64, T=512, S=512, E=512, H=512
typedef __nv_bfloat16 bf16;
typedef __half h16;

// ---------------- scratch (static device globals; no allocs) ----------------
__device__ float g_xi[64L * 512 * 1536];     // input projection [B*T, 3H] fp32
__device__ float g_scores[64L * 512 * 512];  // scores (pre-softmax) fp32
__device__ bf16 g_hbh[2][64 * 512];          // hidden state hi (double buffered)
__device__ bf16 g_hbl[2][64 * 512];          // hidden state lo
__device__ unsigned g_barc[4 * 32];          // per-bg arrival counters (padded)

// fp16 operand buffers (single precision plane)
__device__ h16 g_X16[64L * 512 * 512];
__device__ h16 g_Enc16[64L * 512 * 512];
__device__ h16 g_ET16[64L * 512 * 512];
__device__ h16 g_dec16[64L * 512 * 512];
__device__ h16 g_attn16[64L * 512 * 512];
__device__ h16 g_mix16[64L * 512 * 512];
__device__ h16 g_o116[64L * 512 * 512];
__device__ h16 g_Wih16[1536 * 512];
__device__ h16 g_Wao16[512 * 1024];
__device__ h16 g_Wd16[512 * 512];

// ======================================================================
// helpers
// ======================================================================
__device__ __forceinline__ void mma_f16(float* c, const uint32_t* a,
                                        uint32_t b0, uint32_t b1) {
    asm volatile(
        "mma.sync.aligned.m16n8k16.row.col.f32.f16.f16.f32 "
        "{%0,%1,%2,%3}, {%4,%5,%6,%7}, {%8,%9}, {%0,%1,%2,%3};"
        : "+f"(c[0]), "+f"(c[1]), "+f"(c[2]), "+f"(c[3])
        : "r"(a[0]), "r"(a[1]), "r"(a[2]), "r"(a[3]), "r"(b0), "r"(b1));
}

__device__ __forceinline__ void mma_bf16(float* c, const uint32_t* a,
                                         uint32_t b0, uint32_t b1) {
    asm volatile(
        "mma.sync.aligned.m16n8k16.row.col.f32.bf16.bf16.f32 "
        "{%0,%1,%2,%3}, {%4,%5,%6,%7}, {%8,%9}, {%0,%1,%2,%3};"
        : "+f"(c[0]), "+f"(c[1]), "+f"(c[2]), "+f"(c[3])
        : "r"(a[0]), "r"(a[1]), "r"(a[2]), "r"(a[3]), "r"(b0), "r"(b1));
}

__device__ __forceinline__ void ldsm_x4(uint32_t addr, uint32_t& r0, uint32_t& r1,
                                        uint32_t& r2, uint32_t& r3) {
    asm volatile("ldmatrix.sync.aligned.m8n8.x4.shared.b16 {%0,%1,%2,%3}, [%4];"
                 : "=r"(r0), "=r"(r1), "=r"(r2), "=r"(r3) : "r"(addr));
}

__device__ __forceinline__ uint32_t cvta_smem(const void* p) {
    uint32_t a;
    asm("{ .reg .u64 t; cvta.to.shared.u64 t, %1; cvt.u32.u64 %0, t; }"
        : "=r"(a) : "l"(p));
    return a;
}

__device__ __forceinline__ void cp16(uint32_t dst, const void* src) {
    asm volatile("cp.async.cg.shared.global [%0], [%1], 16;"
                 :: "r"(dst), "l"(src));
}
#define CP_COMMIT() asm volatile("cp.async.commit_group;" ::: "memory")
#define CP_WAIT0() asm volatile("cp.async.wait_group 0;" ::: "memory")

__device__ __forceinline__ void cvt4(const float4 x, uint32_t& hi, uint32_t& hi2,
                                     uint32_t& lo, uint32_t& lo2) {
    __nv_bfloat162 h0 = __floats2bfloat162_rn(x.x, x.y);
    __nv_bfloat162 h1 = __floats2bfloat162_rn(x.z, x.w);
    __nv_bfloat162 l0 = __floats2bfloat162_rn(x.x - __bfloat162float(h0.x),
                                              x.y - __bfloat162float(h0.y));
    __nv_bfloat162 l1 = __floats2bfloat162_rn(x.z - __bfloat162float(h1.x),
                                              x.w - __bfloat162float(h1.y));
    hi = *reinterpret_cast<uint32_t*>(&h0);
    hi2 = *reinterpret_cast<uint32_t*>(&h1);
    lo = *reinterpret_cast<uint32_t*>(&l0);
    lo2 = *reinterpret_cast<uint32_t*>(&l1);
}

// ======================================================================
// cvt pass: fp32 -> fp16
// ======================================================================
__global__ void __launch_bounds__(256) cvt_k(const float* __restrict__ src,
                                             h16* __restrict__ d, long n4)
{
    long i = (long)blockIdx.x * 256 + threadIdx.x;
    long stride = (long)gridDim.x * 256;
    for (; i < n4; i += stride) {
        float4 x = *(const float4*)(src + i * 4);
        __half2 a = __floats2half2_rn(x.x, x.y);
        __half2 b = __floats2half2_rn(x.z, x.w);
        *(uint2*)(d + i * 4) = make_uint2(*reinterpret_cast<uint32_t*>(&a),
                                          *reinterpret_cast<uint32_t*>(&b));
    }
}

// ======================================================================
// Enc prep: Enc [B,S,H] fp32 -> Enc16 (same layout) + ET16 ([B,H,S])
// ======================================================================
__global__ void __launch_bounds__(256) encprep_k(const float* __restrict__ src,
                                                 h16* __restrict__ e16,
                                                 h16* __restrict__ t16)
{
    __shared__ float t[32][33];
    const int b = blockIdx.z;
    const int s0 = blockIdx.y * 32, h0 = blockIdx.x * 32;
    const long base = (long)b << 18;
    const int x = threadIdx.x, y = threadIdx.y;
#pragma unroll
    for (int i = 0; i < 32; i += 8) {
        float v = src[base + (long)(s0 + y + i) * 512 + h0 + x];
        t[y + i][x] = v;
        e16[base + (long)(s0 + y + i) * 512 + h0 + x] = __float2half(v);
    }
    __syncthreads();
#pragma unroll
    for (int i = 0; i < 32; i += 8)
        t16[base + (long)(h0 + y + i) * 512 + s0 + x] = __float2half(t[x][y + i]);
}

// ======================================================================
// fp16 HMMA GEMM: cp.async 2-stage pipeline, K-chunk 32, ldmatrix.
// (unchanged from R12 — known good)
// ======================================================================
#define APC2 40
#define PLANE2_B (128 * APC2 * 2)
#define STAGE2_B (2 * PLANE2_B)
#define TGB_SMEM (2 * STAGE2_B)

template <int ACT, int OBF>
__global__ void __launch_bounds__(256, 2) tgemm_16(
    const h16* __restrict__ A, const h16* __restrict__ A2, int ksplit, int lda,
    const h16* __restrict__ B, int ldb,
    const float* __restrict__ bias,
    float* __restrict__ C, h16* __restrict__ C16, int ldc,
    int K, long sA, long sB, long sC)
{
    extern __shared__ char smraw[];
    const uint32_t smb = cvta_smem(smraw);

    const int tid = threadIdx.x, wid = tid >> 5, lane = tid & 31;
    const int m0 = blockIdx.y * 128, n0 = blockIdx.x * 128;
    const long zb = blockIdx.z;
    A += zb * sA; A2 += zb * sA; B += zb * sB;
    if (OBF) C16 += zb * sC; else C += zb * sC;

    const int wm = wid & 3, wn = wid >> 2;
    const int lr = lane >> 2;

    const uint32_t a_off = ((uint32_t)(wm * 32 + (lane & 15)) * APC2 +
                            (uint32_t)((lane >> 4) << 3)) * 2u;
    const uint32_t b_off = ((uint32_t)(wn * 64 + ((lane >> 4) << 3) + (lane & 7)) * APC2 +
                            (uint32_t)(((lane >> 3) & 1) << 3)) * 2u;

    const int ldrow = tid >> 1;
    const int ldc0 = (tid & 1) * 16;

    const int nch = K >> 5;

    auto issue = [&](int ch) {
        if (ch < nch) {
            const int kg = ch << 5;
            const h16* a = A;
            int kc = kg;
            if (kg >= ksplit) { a = A2; kc = kg - ksplit; }
            const uint32_t stb = smb + (uint32_t)(ch & 1) * STAGE2_B +
                                 (uint32_t)(ldrow * (APC2 * 2) + ldc0 * 2);
            const h16* sa = a + (long)(m0 + ldrow) * lda + kc + ldc0;
            const h16* sb = B + (long)(n0 + ldrow) * ldb + kg + ldc0;
            cp16(stb, sa);            cp16(stb + 16, sa + 8);
            cp16(stb + PLANE2_B, sb); cp16(stb + PLANE2_B + 16, sb + 8);
        }
        CP_COMMIT();
    };

    float acc[2][8][4];
#pragma unroll
    for (int mi = 0; mi < 2; mi++)
#pragma unroll
        for (int ni = 0; ni < 8; ni++)
#pragma unroll
            for (int q = 0; q < 4; q++) acc[mi][ni][q] = 0.f;

    issue(0);

    for (int ch = 0; ch < nch; ++ch) {
        CP_WAIT0();
        __syncthreads();
        issue(ch + 1);

        const uint32_t AA = smb + (uint32_t)(ch & 1) * STAGE2_B;
        const uint32_t BA = AA + PLANE2_B;

#pragma unroll
        for (int ks = 0; ks < 2; ++ks) {
            const uint32_t kb = (uint32_t)(ks * 16) * 2u;
            uint32_t afr[2][4];
#pragma unroll
            for (int mi = 0; mi < 2; mi++) {
                uint32_t ao = a_off + (uint32_t)(mi * 16 * APC2) * 2u + kb;
                ldsm_x4(AA + ao, afr[mi][0], afr[mi][1], afr[mi][2], afr[mi][3]);
            }
#pragma unroll
            for (int p = 0; p < 4; p++) {
                uint32_t bo = b_off + (uint32_t)(p * 16 * APC2) * 2u + kb;
                uint32_t b0, b1, b2, b3;
                ldsm_x4(BA + bo, b0, b1, b2, b3);
#pragma unroll
                for (int mi = 0; mi < 2; mi++) {
                    mma_f16(acc[mi][2 * p + 0], afr[mi], b0, b1);
                    mma_f16(acc[mi][2 * p + 1], afr[mi], b2, b3);
                }
            }
        }
    }

    // ---- epilogue ----
#pragma unroll
    for (int mi = 0; mi < 2; mi++) {
#pragma unroll
        for (int ni = 0; ni < 8; ni++) {
            int n = n0 + wn * 64 + ni * 8 + (lane & 3) * 2;
            float b0 = 0.f, b1 = 0.f;
            if (ACT >= 1) { b0 = bias[n]; b1 = bias[n + 1]; }
#pragma unroll
            for (int half = 0; half < 2; half++) {
                int m = m0 + wm * 32 + mi * 16 + lr + half * 8;
                float v0 = acc[mi][ni][half * 2 + 0] + b0;
                float v1 = acc[mi][ni][half * 2 + 1] + b1;
                if (ACT == 2) { v0 = tanhf(v0); v1 = tanhf(v1); }
                if (OBF) {
                    __half2 hv = __floats2half2_rn(v0, v1);
                    *(uint32_t*)(C16 + (long)m * ldc + n) =
                        *reinterpret_cast<uint32_t*>(&hv);
                } else {
                    *(float2*)(C + (long)m * ldc + n) = make_float2(v0, v1);
                }
            }
        }
    }
}

// ======================================================================
// Persistent tensor-core GRU scan. 512 threads / 16 warps, K=32 per warp.
// W fragments hoisted into registers (loop-invariant): no W ldsm in loop.
// Split-bf16 internals (accuracy-critical); dec written fp16.
// ======================================================================
#define HL_OFF (16 * 520 * 2)
#define GRU_SMEM_BYTES ((2 * 48 * 520 + 2 * 16 * 520) * 2 + (16 * 800) * 4)

__global__ void __launch_bounds__(512) gru_scan(const float* __restrict__ Whh,
                                                const float* __restrict__ bhh)
{
    extern __shared__ char smg[];
    bf16* Wh = (bf16*)smg;                  // [48][520]
    bf16* Wl = Wh + 48 * 520;
    bf16* Hh = Wl + 48 * 520;               // [16][520]
    bf16* Hl = Hh + 16 * 520;
    float* Red = (float*)(Hl + 16 * 520);   // [16][800] (row stride 50)

    const uint32_t WhA = cvta_smem(Wh), WlA = cvta_smem(Wl);
    const uint32_t HhA = cvta_smem(Hh);

    const int tid = threadIdx.x;
    const int bg = blockIdx.x >> 5;
    const int jg = blockIdx.x & 31;
    const int b0 = bg * 16, j0 = jg * 16;

    // W slice load + hi/lo split (once)
    for (int v = tid; v < 48 * 128; v += 512) {
        int rowid = v >> 7, kc = (v & 127) << 2;
        int gate = rowid >> 4, jl = rowid & 15;
        float4 x = *(const float4*)(Whh + (long)(gate * 512 + j0 + jl) * 512 + kc);
        uint32_t h0, h1, l0, l1;
        cvt4(x, h0, h1, l0, l1);
        *(uint2*)&Wh[rowid * 520 + kc] = make_uint2(h0, h1);
        *(uint2*)&Wl[rowid * 520 + kc] = make_uint2(l0, l1);
    }
    __syncthreads();

    const int warp = tid >> 5, lane = tid & 31;
    const int lr = lane >> 2;
    const int k0w = warp << 5;   // 32-wide K slice per warp

    const uint32_t a_off = ((uint32_t)(lane & 15) * 520 +
                            (uint32_t)((lane >> 4) << 3)) * 2u;
    const uint32_t b_off = ((uint32_t)(((lane >> 4) << 3) + (lane & 7)) * 520 +
                            (uint32_t)(((lane >> 3) & 1) << 3)) * 2u;

    // ---- hoist W fragments into registers (loop-invariant) ----
    uint32_t wfh[2][3][4], wfl[2][3][4];
#pragma unroll
    for (int ks = 0; ks < 2; ++ks) {
        const uint32_t kb = (uint32_t)(k0w + ks * 16) * 2u;
#pragma unroll
        for (int p = 0; p < 3; ++p) {
            uint32_t bo = b_off + (uint32_t)(p * 16 * 520) * 2u + kb;
            ldsm_x4(WhA + bo, wfh[ks][p][0], wfh[ks][p][1], wfh[ks][p][2], wfh[ks][p][3]);
            ldsm_x4(WlA + bo, wfl[ks][p][0], wfl[ks][p][1], wfl[ks][p][2], wfl[ks][p][3]);
        }
    }

    const int blc = tid >> 4, jlc = tid & 15;   // combine mapping (tid < 256 only)
    const bool comb = (tid < 256);
    float br = 0.f, bz = 0.f, bnn = 0.f;
    int bglob = b0, jglob = j0;
    long xibase = 0, hidx = 0;
    if (comb) {
        br = bhh[j0 + jlc];
        bz = bhh[512 + j0 + jlc];
        bnn = bhh[1024 + j0 + jlc];
        bglob = b0 + blc; jglob = j0 + jlc;
        xibase = (long)bglob * 512 * 1536 + jglob;
        hidx = (long)bglob * 512 + jglob;
    }
    volatile unsigned* barp = &g_barc[bg * 32];

    for (int t = 0; t < 512; ++t) {
        const bf16* hsh = g_hbh[t & 1];
        const bf16* hsl = g_hbl[t & 1];
        bf16* hnh = g_hbh[(t & 1) ^ 1];
        bf16* hnl = g_hbl[(t & 1) ^ 1];

        // prefetch xi (DRAM; independent of h_t)
        float xr = 0.f, xz = 0.f, xn = 0.f;
        if (comb) {
            const long xio = xibase + (long)t * 1536;
            xr = g_xi[xio];
            xz = g_xi[xio + 512];
            xn = g_xi[xio + 1024];
        }

        // stage h tile: raw cp.async of bf16 hi/lo planes
#pragma unroll
        for (int i = 0; i < 2; i++) {
            int g = tid + i * 512;             // 0..1023 granules (16B)
            int r = g >> 6, kc8 = (g & 63) << 3;
            uint32_t dst = HhA + (uint32_t)(r * 1040 + kc8 * 2);
            cp16(dst, hsh + (b0 + r) * 512 + kc8);
            cp16(dst + HL_OFF, hsl + (b0 + r) * 512 + kc8);
        }
        CP_COMMIT();
        CP_WAIT0();
        __syncthreads();

        // MMA: M=16 x N=48 x K=32 (per-warp K slice); W frags in registers
        float acc[6][4];
#pragma unroll
        for (int ni = 0; ni < 6; ni++)
#pragma unroll
            for (int q = 0; q < 4; q++) acc[ni][q] = 0.f;

#pragma unroll
        for (int ks = 0; ks < 2; ++ks) {
            const uint32_t kb = (uint32_t)(k0w + ks * 16) * 2u;
            uint32_t ah[4], al[4];
            ldsm_x4(HhA + a_off + kb, ah[0], ah[1], ah[2], ah[3]);
            ldsm_x4(HhA + HL_OFF + a_off + kb, al[0], al[1], al[2], al[3]);
#pragma unroll
            for (int p = 0; p < 3; ++p) {
                mma_bf16(acc[2 * p + 0], ah, wfh[ks][p][0], wfh[ks][p][1]);
                mma_bf16(acc[2 * p + 0], ah, wfl[ks][p][0], wfl[ks][p][1]);
                mma_bf16(acc[2 * p + 0], al, wfh[ks][p][0], wfh[ks][p][1]);
                mma_bf16(acc[2 * p + 1], ah, wfh[ks][p][2], wfh[ks][p][3]);
                mma_bf16(acc[2 * p + 1], ah, wfl[ks][p][2], wfl[ks][p][3]);
                mma_bf16(acc[2 * p + 1], al, wfh[ks][p][2], wfh[ks][p][3]);
            }
        }

        float* rw = Red + warp * 800;
#pragma unroll
        for (int ni = 0; ni < 6; ++ni) {
            int n = ni * 8 + (lane & 3) * 2;
            *(float2*)&rw[lr * 50 + n] = make_float2(acc[ni][0], acc[ni][1]);
            *(float2*)&rw[(lr + 8) * 50 + n] = make_float2(acc[ni][2], acc[ni][3]);
        }
        __syncthreads();

        // combine: one (b,j) per thread (tid < 256)
        float hnew = 0.f;
        if (comb) {
            float hr = br, hz = bz, hn = bnn;
#pragma unroll
            for (int w = 0; w < 16; ++w) {
                hr += Red[w * 800 + blc * 50 + jlc];
                hz += Red[w * 800 + blc * 50 + 16 + jlc];
                hn += Red[w * 800 + blc * 50 + 32 + jlc];
            }
            float hold = __bfloat162float(Hh[blc * 520 + jglob]) +
                         __bfloat162float(Hl[blc * 520 + jglob]);
            float r = __fdividef(1.f, 1.f + __expf(-(xr + hr)));
            float z = __fdividef(1.f, 1.f + __expf(-(xz + hz)));
            float e2 = __expf(2.f * (xn + r * hn));
            float n = __fdividef(e2 - 1.f, e2 + 1.f);
            hnew = (1.f - z) * n + z * hold;

            bf16 hhi = __float2bfloat16(hnew);
            bf16 hlo = __float2bfloat16(hnew - __bfloat162float(hhi));
            hnh[hidx] = hhi;
            hnl[hidx] = hlo;
        }

        // ---- per-bg barrier: monotonic counter, direct poll ----
        __syncthreads();
        if (tid == 0) {
            __threadfence();
            atomicAdd(&g_barc[bg * 32], 1u);
        }
        if (comb) {   // dec fp16 store — off the fence/arrive critical path
            g_dec16[((long)(bglob * 512 + t)) * 512 + jglob] = __float2half(hnew);
        }
        if (tid == 0) {
            unsigned want = ((unsigned)t + 1u) * 32u;
            while (*barp < want) { }
            __threadfence();
        }
        __syncthreads();
    }
}

// ======================================================================
// Softmax over S=512 per (b,t) row, mask-aware; writes attn fp16.
// ======================================================================
__global__ void __launch_bounds__(256) softmax_k(const float* __restrict__ sc,
                                                 const unsigned char* __restrict__ mask)
{
    const int row = blockIdx.x;
    const int b = row >> 9;
    const float* p = sc + (long)row * 512;
    const unsigned char* mp = mask + b * 512;
    const int tid = threadIdx.x;

    const float NEG_INF = -__int_as_float(0x7f800000);
    float v0 = p[tid], v1 = p[tid + 256];
    bool m0 = mp[tid] != 0, m1 = mp[tid + 256] != 0;
    if (m0) v0 = NEG_INF;
    if (m1) v1 = NEG_INF;

    __shared__ float red[8];
    __shared__ float bcast;

    float mx = fmaxf(v0, v1);
#pragma unroll
    for (int o = 16; o; o >>= 1) mx = fmaxf(mx, __shfl_xor_sync(0xffffffffu, mx, o));
    if ((tid & 31) == 0) red[tid >> 5] = mx;
    __syncthreads();
    if (tid < 8) {
        float x = red[tid];
#pragma unroll
        for (int o = 4; o; o >>= 1) x = fmaxf(x, __shfl_xor_sync(0xffu, x, o));
        if (tid == 0) bcast = x;
    }
    __syncthreads();
    mx = bcast;

    float e0 = m0 ? 0.f : __expf(v0 - mx);
    float e1 = m1 ? 0.f : __expf(v1 - mx);
    float s = e0 + e1;
#pragma unroll
    for (int o = 16; o; o >>= 1) s += __shfl_xor_sync(0xffffffffu, s, o);
    if ((tid & 31) == 0) red[tid >> 5] = s;
    __syncthreads();
    if (tid < 8) {
        float x = red[tid];
#pragma unroll
        for (int o = 4; o; o >>= 1) x += __shfl_xor_sync(0xffu, x, o);
        if (tid == 0) bcast = x;
    }
    __syncthreads();
    float inv = 1.f / bcast;
    long base = (long)row * 512;
    g_attn16[base + tid] = __float2half(e0 * inv);
    g_attn16[base + tid + 256] = __float2half(e1 * inv);
}

__global__ void __launch_bounds__(256) copy_h_k(float* __restrict__ dst)
{
    int i = blockIdx.x * 256 + threadIdx.x;
    if (i < 64 * 512)
        dst[i] = __bfloat162float(g_hbh[0][i]) + __bfloat162float(g_hbl[0][i]);
}

// ======================================================================
// launch
// ======================================================================
extern "C" void kernel_launch(void* const* d_in, const int* in_sizes, int n_in,
                              void* d_out, int out_size)
{
    const float* X    = (const float*)d_in[0];
    const float* Enc  = (const float*)d_in[1];
    const unsigned char* Mask = (const unsigned char*)d_in[2];
    const float* Wih  = (const float*)d_in[3];
    const float* Whh  = (const float*)d_in[4];
    const float* bih  = (const float*)d_in[5];
    const float* bhh  = (const float*)d_in[6];
    const float* Wao  = (const float*)d_in[7];
    const float* bao  = (const float*)d_in[8];
    const float* Wd   = (const float*)d_in[9];
    const float* bd   = (const float*)d_in[10];
    float* out = (float*)d_out;

    void *p_xi, *p_sc, *p_hh, *p_hl, *p_barc;
    cudaGetSymbolAddress(&p_xi, g_xi);
    cudaGetSymbolAddress(&p_sc, g_scores);
    cudaGetSymbolAddress(&p_hh, g_hbh);
    cudaGetSymbolAddress(&p_hl, g_hbl);
    cudaGetSymbolAddress(&p_barc, g_barc);
    float* xi = (float*)p_xi;
    float* sc = (float*)p_sc;

#define GET(sym) ({ void* _p; cudaGetSymbolAddress(&_p, sym); (h16*)_p; })
    h16 *X16 = GET(g_X16);
    h16 *E16 = GET(g_Enc16);
    h16 *T16 = GET(g_ET16);
    h16 *D16 = GET(g_dec16);
    h16 *At16 = GET(g_attn16);
    h16 *M16 = GET(g_mix16);
    h16 *O16 = GET(g_o116);
    h16 *Wih16 = GET(g_Wih16);
    h16 *Wao16 = GET(g_Wao16);
    h16 *Wd16 = GET(g_Wd16);
#undef GET

    cudaFuncSetAttribute(gru_scan, cudaFuncAttributeMaxDynamicSharedMemorySize, GRU_SMEM_BYTES);
    cudaFuncSetAttribute(tgemm_16<1, 0>, cudaFuncAttributeMaxDynamicSharedMemorySize, TGB_SMEM);
    cudaFuncSetAttribute(tgemm_16<0, 0>, cudaFuncAttributeMaxDynamicSharedMemorySize, TGB_SMEM);
    cudaFuncSetAttribute(tgemm_16<0, 1>, cudaFuncAttributeMaxDynamicSharedMemorySize, TGB_SMEM);
    cudaFuncSetAttribute(tgemm_16<2, 1>, cudaFuncAttributeMaxDynamicSharedMemorySize, TGB_SMEM);

    // h0 = 0 (buffer 0 read at t=0); barrier counters = 0 — every launch
    cudaMemsetAsync((char*)p_hh, 0, 64 * 512 * sizeof(bf16));
    cudaMemsetAsync((char*)p_hl, 0, 64 * 512 * sizeof(bf16));
    cudaMemsetAsync(p_barc, 0, 4 * 32 * sizeof(unsigned));

    const int KBIG = 1 << 30;

    // 0) operand prep (fp16)
    cvt_k<<<512, 256>>>(X, X16, (64L * 512 * 512) / 4);
    cvt_k<<<64, 256>>>(Wih, Wih16, (1536L * 512) / 4);
    cvt_k<<<64, 256>>>(Wao, Wao16, (512L * 1024) / 4);
    cvt_k<<<32, 256>>>(Wd, Wd16, (512L * 512) / 4);
    encprep_k<<<dim3(16, 16, 64), dim3(32, 8)>>>(Enc, E16, T16);

    // 1) xi = X @ Wih^T + bih : [32768,1536] fp32
    tgemm_16<1, 0><<<dim3(12, 256, 1), 256, TGB_SMEM>>>(
        X16, X16, KBIG, 512, Wih16, 512, bih,
        xi, nullptr, 1536, 512, 0, 0, 0);

    // 2) GRU scan -> dec fp16, h_last in g_hbh/g_hbl[0]
    gru_scan<<<128, 512, GRU_SMEM_BYTES>>>(Whh, bhh);

    // 3) scores[b] = dec[b] @ enc[b]^T : fp32
    tgemm_16<0, 0><<<dim3(4, 4, 64), 256, TGB_SMEM>>>(
        D16, D16, KBIG, 512, E16, 512, nullptr,
        sc, nullptr, 512, 512, 262144L, 262144L, 262144L);

    // 4) softmax (mask) -> attn fp16
    softmax_k<<<64 * 512, 256>>>(sc, Mask);

    // 5) mix[b] = attn[b] @ encT[b]^T : fp16 out
    tgemm_16<0, 1><<<dim3(4, 4, 64), 256, TGB_SMEM>>>(
        At16, At16, KBIG, 512, T16, 512, nullptr,
        nullptr, M16, 512, 512, 262144L, 262144L, 262144L);

    // 6) o1 = tanh(concat(mix, dec) @ Wao^T + bao) : fp16 out, K=1024
    tgemm_16<2, 1><<<dim3(4, 256, 1), 256, TGB_SMEM>>>(
        M16, D16, 512, 512, Wao16, 1024, bao,
        nullptr, O16, 512, 1024, 0, 0, 0);

    // 7) final = o1 @ Wd^T + bd -> d_out fp32
    tgemm_16<1, 0><<<dim3(4, 256, 1), 256, TGB_SMEM>>>(
        O16, O16, KBIG, 512, Wd16, 512, bd,
        out, nullptr, 512, 512, 0, 0, 0);

    // 8) h_last -> tail of d_out
    copy_h_k<<<128, 256>>>(out + (long)out_size - 64 * 512);
}

// round 14
// speedup vs baseline: 1.0542x; 1.0542x over previous
#include <cuda_runtime.h>
#include <cuda_bf16.h>
#include <cuda_fp16.h>
#include <math.h>
#include <stdint.h>

// Problem constants: B=64, T=512, S=512, E=512, H=512
typedef __nv_bfloat16 bf16;
typedef __half h16;

// ---------------- scratch (static device globals; no allocs) ----------------
__device__ float g_xi[64L * 512 * 1536];     // input projection [B*T, 3H] fp32
__device__ float g_scores[64L * 512 * 512];  // scores (pre-softmax) fp32
__device__ bf16 g_hbh[2][64 * 512];          // hidden state hi (double buffered)
__device__ bf16 g_hbl[2][64 * 512];          // hidden state lo
__device__ unsigned g_barc[4 * 32];          // per-bg arrival counters (padded)

// fp16 operand buffers (single precision plane)
__device__ h16 g_X16[64L * 512 * 512];
__device__ h16 g_Enc16[64L * 512 * 512];
__device__ h16 g_ET16[64L * 512 * 512];
__device__ h16 g_dec16[64L * 512 * 512];
__device__ h16 g_attn16[64L * 512 * 512];
__device__ h16 g_mix16[64L * 512 * 512];
__device__ h16 g_o116[64L * 512 * 512];
__device__ h16 g_Wih16[1536 * 512];
__device__ h16 g_Wao16[512 * 1024];
__device__ h16 g_Wd16[512 * 512];

// ======================================================================
// helpers
// ======================================================================
__device__ __forceinline__ void mma_f16(float* c, const uint32_t* a,
                                        uint32_t b0, uint32_t b1) {
    asm volatile(
        "mma.sync.aligned.m16n8k16.row.col.f32.f16.f16.f32 "
        "{%0,%1,%2,%3}, {%4,%5,%6,%7}, {%8,%9}, {%0,%1,%2,%3};"
        : "+f"(c[0]), "+f"(c[1]), "+f"(c[2]), "+f"(c[3])
        : "r"(a[0]), "r"(a[1]), "r"(a[2]), "r"(a[3]), "r"(b0), "r"(b1));
}

__device__ __forceinline__ void mma_bf16(float* c, const uint32_t* a,
                                         uint32_t b0, uint32_t b1) {
    asm volatile(
        "mma.sync.aligned.m16n8k16.row.col.f32.bf16.bf16.f32 "
        "{%0,%1,%2,%3}, {%4,%5,%6,%7}, {%8,%9}, {%0,%1,%2,%3};"
        : "+f"(c[0]), "+f"(c[1]), "+f"(c[2]), "+f"(c[3])
        : "r"(a[0]), "r"(a[1]), "r"(a[2]), "r"(a[3]), "r"(b0), "r"(b1));
}

__device__ __forceinline__ void ldsm_x4(uint32_t addr, uint32_t& r0, uint32_t& r1,
                                        uint32_t& r2, uint32_t& r3) {
    asm volatile("ldmatrix.sync.aligned.m8n8.x4.shared.b16 {%0,%1,%2,%3}, [%4];"
                 : "=r"(r0), "=r"(r1), "=r"(r2), "=r"(r3) : "r"(addr));
}

__device__ __forceinline__ uint32_t cvta_smem(const void* p) {
    uint32_t a;
    asm("{ .reg .u64 t; cvta.to.shared.u64 t, %1; cvt.u32.u64 %0, t; }"
        : "=r"(a) : "l"(p));
    return a;
}

__device__ __forceinline__ void cp16(uint32_t dst, const void* src) {
    asm volatile("cp.async.cg.shared.global [%0], [%1], 16;"
                 :: "r"(dst), "l"(src));
}
#define CP_COMMIT() asm volatile("cp.async.commit_group;" ::: "memory")
#define CP_WAIT0() asm volatile("cp.async.wait_group 0;" ::: "memory")

__device__ __forceinline__ void cvt4(const float4 x, uint32_t& hi, uint32_t& hi2,
                                     uint32_t& lo, uint32_t& lo2) {
    __nv_bfloat162 h0 = __floats2bfloat162_rn(x.x, x.y);
    __nv_bfloat162 h1 = __floats2bfloat162_rn(x.z, x.w);
    __nv_bfloat162 l0 = __floats2bfloat162_rn(x.x - __bfloat162float(h0.x),
                                              x.y - __bfloat162float(h0.y));
    __nv_bfloat162 l1 = __floats2bfloat162_rn(x.z - __bfloat162float(h1.x),
                                              x.w - __bfloat162float(h1.y));
    hi = *reinterpret_cast<uint32_t*>(&h0);
    hi2 = *reinterpret_cast<uint32_t*>(&h1);
    lo = *reinterpret_cast<uint32_t*>(&l0);
    lo2 = *reinterpret_cast<uint32_t*>(&l1);
}

// ======================================================================
// cvt pass: fp32 -> fp16
// ======================================================================
__global__ void __launch_bounds__(256) cvt_k(const float* __restrict__ src,
                                             h16* __restrict__ d, long n4)
{
    long i = (long)blockIdx.x * 256 + threadIdx.x;
    long stride = (long)gridDim.x * 256;
    for (; i < n4; i += stride) {
        float4 x = *(const float4*)(src + i * 4);
        __half2 a = __floats2half2_rn(x.x, x.y);
        __half2 b = __floats2half2_rn(x.z, x.w);
        *(uint2*)(d + i * 4) = make_uint2(*reinterpret_cast<uint32_t*>(&a),
                                          *reinterpret_cast<uint32_t*>(&b));
    }
}

// ======================================================================
// Enc prep: Enc [B,S,H] fp32 -> Enc16 (same layout) + ET16 ([B,H,S])
// ======================================================================
__global__ void __launch_bounds__(256) encprep_k(const float* __restrict__ src,
                                                 h16* __restrict__ e16,
                                                 h16* __restrict__ t16)
{
    __shared__ float t[32][33];
    const int b = blockIdx.z;
    const int s0 = blockIdx.y * 32, h0 = blockIdx.x * 32;
    const long base = (long)b << 18;
    const int x = threadIdx.x, y = threadIdx.y;
#pragma unroll
    for (int i = 0; i < 32; i += 8) {
        float v = src[base + (long)(s0 + y + i) * 512 + h0 + x];
        t[y + i][x] = v;
        e16[base + (long)(s0 + y + i) * 512 + h0 + x] = __float2half(v);
    }
    __syncthreads();
#pragma unroll
    for (int i = 0; i < 32; i += 8)
        t16[base + (long)(h0 + y + i) * 512 + s0 + x] = __float2half(t[x][y + i]);
}

// ======================================================================
// fp16 HMMA GEMM: cp.async 2-stage pipeline, K-chunk 32, ldmatrix.
// (unchanged from R12 — known good)
// ======================================================================
#define APC2 40
#define PLANE2_B (128 * APC2 * 2)
#define STAGE2_B (2 * PLANE2_B)
#define TGB_SMEM (2 * STAGE2_B)

template <int ACT, int OBF>
__global__ void __launch_bounds__(256, 2) tgemm_16(
    const h16* __restrict__ A, const h16* __restrict__ A2, int ksplit, int lda,
    const h16* __restrict__ B, int ldb,
    const float* __restrict__ bias,
    float* __restrict__ C, h16* __restrict__ C16, int ldc,
    int K, long sA, long sB, long sC)
{
    extern __shared__ char smraw[];
    const uint32_t smb = cvta_smem(smraw);

    const int tid = threadIdx.x, wid = tid >> 5, lane = tid & 31;
    const int m0 = blockIdx.y * 128, n0 = blockIdx.x * 128;
    const long zb = blockIdx.z;
    A += zb * sA; A2 += zb * sA; B += zb * sB;
    if (OBF) C16 += zb * sC; else C += zb * sC;

    const int wm = wid & 3, wn = wid >> 2;
    const int lr = lane >> 2;

    const uint32_t a_off = ((uint32_t)(wm * 32 + (lane & 15)) * APC2 +
                            (uint32_t)((lane >> 4) << 3)) * 2u;
    const uint32_t b_off = ((uint32_t)(wn * 64 + ((lane >> 4) << 3) + (lane & 7)) * APC2 +
                            (uint32_t)(((lane >> 3) & 1) << 3)) * 2u;

    const int ldrow = tid >> 1;
    const int ldc0 = (tid & 1) * 16;

    const int nch = K >> 5;

    auto issue = [&](int ch) {
        if (ch < nch) {
            const int kg = ch << 5;
            const h16* a = A;
            int kc = kg;
            if (kg >= ksplit) { a = A2; kc = kg - ksplit; }
            const uint32_t stb = smb + (uint32_t)(ch & 1) * STAGE2_B +
                                 (uint32_t)(ldrow * (APC2 * 2) + ldc0 * 2);
            const h16* sa = a + (long)(m0 + ldrow) * lda + kc + ldc0;
            const h16* sb = B + (long)(n0 + ldrow) * ldb + kg + ldc0;
            cp16(stb, sa);            cp16(stb + 16, sa + 8);
            cp16(stb + PLANE2_B, sb); cp16(stb + PLANE2_B + 16, sb + 8);
        }
        CP_COMMIT();
    };

    float acc[2][8][4];
#pragma unroll
    for (int mi = 0; mi < 2; mi++)
#pragma unroll
        for (int ni = 0; ni < 8; ni++)
#pragma unroll
            for (int q = 0; q < 4; q++) acc[mi][ni][q] = 0.f;

    issue(0);

    for (int ch = 0; ch < nch; ++ch) {
        CP_WAIT0();
        __syncthreads();
        issue(ch + 1);

        const uint32_t AA = smb + (uint32_t)(ch & 1) * STAGE2_B;
        const uint32_t BA = AA + PLANE2_B;

#pragma unroll
        for (int ks = 0; ks < 2; ++ks) {
            const uint32_t kb = (uint32_t)(ks * 16) * 2u;
            uint32_t afr[2][4];
#pragma unroll
            for (int mi = 0; mi < 2; mi++) {
                uint32_t ao = a_off + (uint32_t)(mi * 16 * APC2) * 2u + kb;
                ldsm_x4(AA + ao, afr[mi][0], afr[mi][1], afr[mi][2], afr[mi][3]);
            }
#pragma unroll
            for (int p = 0; p < 4; p++) {
                uint32_t bo = b_off + (uint32_t)(p * 16 * APC2) * 2u + kb;
                uint32_t b0, b1, b2, b3;
                ldsm_x4(BA + bo, b0, b1, b2, b3);
#pragma unroll
                for (int mi = 0; mi < 2; mi++) {
                    mma_f16(acc[mi][2 * p + 0], afr[mi], b0, b1);
                    mma_f16(acc[mi][2 * p + 1], afr[mi], b2, b3);
                }
            }
        }
    }

    // ---- epilogue ----
#pragma unroll
    for (int mi = 0; mi < 2; mi++) {
#pragma unroll
        for (int ni = 0; ni < 8; ni++) {
            int n = n0 + wn * 64 + ni * 8 + (lane & 3) * 2;
            float b0 = 0.f, b1 = 0.f;
            if (ACT >= 1) { b0 = bias[n]; b1 = bias[n + 1]; }
#pragma unroll
            for (int half = 0; half < 2; half++) {
                int m = m0 + wm * 32 + mi * 16 + lr + half * 8;
                float v0 = acc[mi][ni][half * 2 + 0] + b0;
                float v1 = acc[mi][ni][half * 2 + 1] + b1;
                if (ACT == 2) { v0 = tanhf(v0); v1 = tanhf(v1); }
                if (OBF) {
                    __half2 hv = __floats2half2_rn(v0, v1);
                    *(uint32_t*)(C16 + (long)m * ldc + n) =
                        *reinterpret_cast<uint32_t*>(&hv);
                } else {
                    *(float2*)(C + (long)m * ldc + n) = make_float2(v0, v1);
                }
            }
        }
    }
}

// ======================================================================
// Persistent tensor-core GRU scan. 256 threads / 8 warps, K=64 per warp
// (R12 structure), W fragments hoisted into registers (96 regs; 1 CTA/SM
// allows up to 255). Split-bf16 internals; dec written fp16.
// ======================================================================
#define HL_OFF (16 * 520 * 2)
#define GRU_SMEM_BYTES ((2 * 48 * 520 + 2 * 16 * 520) * 2 + (8 * 800) * 4)

__global__ void __launch_bounds__(256) gru_scan(const float* __restrict__ Whh,
                                                const float* __restrict__ bhh)
{
    extern __shared__ char smg[];
    bf16* Wh = (bf16*)smg;                  // [48][520]
    bf16* Wl = Wh + 48 * 520;
    bf16* Hh = Wl + 48 * 520;               // [16][520]
    bf16* Hl = Hh + 16 * 520;
    float* Red = (float*)(Hl + 16 * 520);   // [8][800] (row stride 50)

    const uint32_t WhA = cvta_smem(Wh), WlA = cvta_smem(Wl);
    const uint32_t HhA = cvta_smem(Hh);

    const int tid = threadIdx.x;
    const int bg = blockIdx.x >> 5;
    const int jg = blockIdx.x & 31;
    const int b0 = bg * 16, j0 = jg * 16;

    // W slice load + hi/lo split (once)
    for (int v = tid; v < 48 * 128; v += 256) {
        int rowid = v >> 7, kc = (v & 127) << 2;
        int gate = rowid >> 4, jl = rowid & 15;
        float4 x = *(const float4*)(Whh + (long)(gate * 512 + j0 + jl) * 512 + kc);
        uint32_t h0, h1, l0, l1;
        cvt4(x, h0, h1, l0, l1);
        *(uint2*)&Wh[rowid * 520 + kc] = make_uint2(h0, h1);
        *(uint2*)&Wl[rowid * 520 + kc] = make_uint2(l0, l1);
    }
    __syncthreads();

    const int warp = tid >> 5, lane = tid & 31;
    const int lr = lane >> 2;
    const int k0w = warp << 6;   // 64-wide K slice per warp

    const uint32_t a_off = ((uint32_t)(lane & 15) * 520 +
                            (uint32_t)((lane >> 4) << 3)) * 2u;
    const uint32_t b_off = ((uint32_t)(((lane >> 4) << 3) + (lane & 7)) * 520 +
                            (uint32_t)(((lane >> 3) & 1) << 3)) * 2u;

    // ---- hoist W fragments into registers (loop-invariant; 96 regs) ----
    uint32_t wfh[4][3][4], wfl[4][3][4];
#pragma unroll
    for (int ks = 0; ks < 4; ++ks) {
        const uint32_t kb = (uint32_t)(k0w + ks * 16) * 2u;
#pragma unroll
        for (int p = 0; p < 3; ++p) {
            uint32_t bo = b_off + (uint32_t)(p * 16 * 520) * 2u + kb;
            ldsm_x4(WhA + bo, wfh[ks][p][0], wfh[ks][p][1], wfh[ks][p][2], wfh[ks][p][3]);
            ldsm_x4(WlA + bo, wfl[ks][p][0], wfl[ks][p][1], wfl[ks][p][2], wfl[ks][p][3]);
        }
    }

    const int blc = tid >> 4, jlc = tid & 15;
    const float br = bhh[j0 + jlc];
    const float bz = bhh[512 + j0 + jlc];
    const float bnn = bhh[1024 + j0 + jlc];
    const int bglob = b0 + blc, jglob = j0 + jlc;
    const long xibase = (long)bglob * 512 * 1536 + jglob;
    const long hidx = (long)bglob * 512 + jglob;
    volatile unsigned* barp = &g_barc[bg * 32];

    for (int t = 0; t < 512; ++t) {
        const bf16* hsh = g_hbh[t & 1];
        const bf16* hsl = g_hbl[t & 1];
        bf16* hnh = g_hbh[(t & 1) ^ 1];
        bf16* hnl = g_hbl[(t & 1) ^ 1];

        // prefetch xi (DRAM; independent of h_t)
        const long xio = xibase + (long)t * 1536;
        float xr = g_xi[xio];
        float xz = g_xi[xio + 512];
        float xn = g_xi[xio + 1024];

        // stage h tile: raw cp.async of bf16 hi/lo planes
#pragma unroll
        for (int i = 0; i < 4; i++) {
            int g = tid + i * 256;
            int r = g >> 6, kc8 = (g & 63) << 3;
            uint32_t dst = HhA + (uint32_t)(r * 1040 + kc8 * 2);
            cp16(dst, hsh + (b0 + r) * 512 + kc8);
            cp16(dst + HL_OFF, hsl + (b0 + r) * 512 + kc8);
        }
        CP_COMMIT();
        CP_WAIT0();
        __syncthreads();

        // MMA: M=16 x N=48 x K=64 (per-warp K slice); W frags in registers
        float acc[6][4];
#pragma unroll
        for (int ni = 0; ni < 6; ni++)
#pragma unroll
            for (int q = 0; q < 4; q++) acc[ni][q] = 0.f;

#pragma unroll
        for (int ks = 0; ks < 4; ++ks) {
            const uint32_t kb = (uint32_t)(k0w + ks * 16) * 2u;
            uint32_t ah[4], al[4];
            ldsm_x4(HhA + a_off + kb, ah[0], ah[1], ah[2], ah[3]);
            ldsm_x4(HhA + HL_OFF + a_off + kb, al[0], al[1], al[2], al[3]);
#pragma unroll
            for (int p = 0; p < 3; ++p) {
                mma_bf16(acc[2 * p + 0], ah, wfh[ks][p][0], wfh[ks][p][1]);
                mma_bf16(acc[2 * p + 0], ah, wfl[ks][p][0], wfl[ks][p][1]);
                mma_bf16(acc[2 * p + 0], al, wfh[ks][p][0], wfh[ks][p][1]);
                mma_bf16(acc[2 * p + 1], ah, wfh[ks][p][2], wfh[ks][p][3]);
                mma_bf16(acc[2 * p + 1], ah, wfl[ks][p][2], wfl[ks][p][3]);
                mma_bf16(acc[2 * p + 1], al, wfh[ks][p][2], wfh[ks][p][3]);
            }
        }

        float* rw = Red + warp * 800;
#pragma unroll
        for (int ni = 0; ni < 6; ++ni) {
            int n = ni * 8 + (lane & 3) * 2;
            *(float2*)&rw[lr * 50 + n] = make_float2(acc[ni][0], acc[ni][1]);
            *(float2*)&rw[(lr + 8) * 50 + n] = make_float2(acc[ni][2], acc[ni][3]);
        }
        __syncthreads();

        // combine: one (b,j) per thread
        float hr = br, hz = bz, hn = bnn;
#pragma unroll
        for (int w = 0; w < 8; ++w) {
            hr += Red[w * 800 + blc * 50 + jlc];
            hz += Red[w * 800 + blc * 50 + 16 + jlc];
            hn += Red[w * 800 + blc * 50 + 32 + jlc];
        }
        float hold = __bfloat162float(Hh[blc * 520 + jglob]) +
                     __bfloat162float(Hl[blc * 520 + jglob]);
        float r = __fdividef(1.f, 1.f + __expf(-(xr + hr)));
        float z = __fdividef(1.f, 1.f + __expf(-(xz + hz)));
        float e2 = __expf(2.f * (xn + r * hn));
        float n = __fdividef(e2 - 1.f, e2 + 1.f);
        float hnew = (1.f - z) * n + z * hold;

        bf16 hhi = __float2bfloat16(hnew);
        bf16 hlo = __float2bfloat16(hnew - __bfloat162float(hhi));
        hnh[hidx] = hhi;
        hnl[hidx] = hlo;

        // ---- per-bg barrier: monotonic counter, direct poll ----
        __syncthreads();
        if (tid == 0) {
            __threadfence();
            atomicAdd(&g_barc[bg * 32], 1u);
        }
        {   // dec fp16 store — off the fence/arrive critical path
            g_dec16[((long)(bglob * 512 + t)) * 512 + jglob] = __float2half(hnew);
        }
        if (tid == 0) {
            unsigned want = ((unsigned)t + 1u) * 32u;
            while (*barp < want) { }
            __threadfence();
        }
        __syncthreads();
    }
}

// ======================================================================
// Softmax over S=512 per (b,t) row, mask-aware; writes attn fp16.
// ======================================================================
__global__ void __launch_bounds__(256) softmax_k(const float* __restrict__ sc,
                                                 const unsigned char* __restrict__ mask)
{
    const int row = blockIdx.x;
    const int b = row >> 9;
    const float* p = sc + (long)row * 512;
    const unsigned char* mp = mask + b * 512;
    const int tid = threadIdx.x;

    const float NEG_INF = -__int_as_float(0x7f800000);
    float v0 = p[tid], v1 = p[tid + 256];
    bool m0 = mp[tid] != 0, m1 = mp[tid + 256] != 0;
    if (m0) v0 = NEG_INF;
    if (m1) v1 = NEG_INF;

    __shared__ float red[8];
    __shared__ float bcast;

    float mx = fmaxf(v0, v1);
#pragma unroll
    for (int o = 16; o; o >>= 1) mx = fmaxf(mx, __shfl_xor_sync(0xffffffffu, mx, o));
    if ((tid & 31) == 0) red[tid >> 5] = mx;
    __syncthreads();
    if (tid < 8) {
        float x = red[tid];
#pragma unroll
        for (int o = 4; o; o >>= 1) x = fmaxf(x, __shfl_xor_sync(0xffu, x, o));
        if (tid == 0) bcast = x;
    }
    __syncthreads();
    mx = bcast;

    float e0 = m0 ? 0.f : __expf(v0 - mx);
    float e1 = m1 ? 0.f : __expf(v1 - mx);
    float s = e0 + e1;
#pragma unroll
    for (int o = 16; o; o >>= 1) s += __shfl_xor_sync(0xffffffffu, s, o);
    if ((tid & 31) == 0) red[tid >> 5] = s;
    __syncthreads();
    if (tid < 8) {
        float x = red[tid];
#pragma unroll
        for (int o = 4; o; o >>= 1) x += __shfl_xor_sync(0xffu, x, o);
        if (tid == 0) bcast = x;
    }
    __syncthreads();
    float inv = 1.f / bcast;
    long base = (long)row * 512;
    g_attn16[base + tid] = __float2half(e0 * inv);
    g_attn16[base + tid + 256] = __float2half(e1 * inv);
}

__global__ void __launch_bounds__(256) copy_h_k(float* __restrict__ dst)
{
    int i = blockIdx.x * 256 + threadIdx.x;
    if (i < 64 * 512)
        dst[i] = __bfloat162float(g_hbh[0][i]) + __bfloat162float(g_hbl[0][i]);
}

// ======================================================================
// launch
// ======================================================================
extern "C" void kernel_launch(void* const* d_in, const int* in_sizes, int n_in,
                              void* d_out, int out_size)
{
    const float* X    = (const float*)d_in[0];
    const float* Enc  = (const float*)d_in[1];
    const unsigned char* Mask = (const unsigned char*)d_in[2];
    const float* Wih  = (const float*)d_in[3];
    const float* Whh  = (const float*)d_in[4];
    const float* bih  = (const float*)d_in[5];
    const float* bhh  = (const float*)d_in[6];
    const float* Wao  = (const float*)d_in[7];
    const float* bao  = (const float*)d_in[8];
    const float* Wd   = (const float*)d_in[9];
    const float* bd   = (const float*)d_in[10];
    float* out = (float*)d_out;

    void *p_xi, *p_sc, *p_hh, *p_hl, *p_barc;
    cudaGetSymbolAddress(&p_xi, g_xi);
    cudaGetSymbolAddress(&p_sc, g_scores);
    cudaGetSymbolAddress(&p_hh, g_hbh);
    cudaGetSymbolAddress(&p_hl, g_hbl);
    cudaGetSymbolAddress(&p_barc, g_barc);
    float* xi = (float*)p_xi;
    float* sc = (float*)p_sc;

#define GET(sym) ({ void* _p; cudaGetSymbolAddress(&_p, sym); (h16*)_p; })
    h16 *X16 = GET(g_X16);
    h16 *E16 = GET(g_Enc16);
    h16 *T16 = GET(g_ET16);
    h16 *D16 = GET(g_dec16);
    h16 *At16 = GET(g_attn16);
    h16 *M16 = GET(g_mix16);
    h16 *O16 = GET(g_o116);
    h16 *Wih16 = GET(g_Wih16);
    h16 *Wao16 = GET(g_Wao16);
    h16 *Wd16 = GET(g_Wd16);
#undef GET

    cudaFuncSetAttribute(gru_scan, cudaFuncAttributeMaxDynamicSharedMemorySize, GRU_SMEM_BYTES);
    cudaFuncSetAttribute(tgemm_16<1, 0>, cudaFuncAttributeMaxDynamicSharedMemorySize, TGB_SMEM);
    cudaFuncSetAttribute(tgemm_16<0, 0>, cudaFuncAttributeMaxDynamicSharedMemorySize, TGB_SMEM);
    cudaFuncSetAttribute(tgemm_16<0, 1>, cudaFuncAttributeMaxDynamicSharedMemorySize, TGB_SMEM);
    cudaFuncSetAttribute(tgemm_16<2, 1>, cudaFuncAttributeMaxDynamicSharedMemorySize, TGB_SMEM);

    // h0 = 0 (buffer 0 read at t=0); barrier counters = 0 — every launch
    cudaMemsetAsync((char*)p_hh, 0, 64 * 512 * sizeof(bf16));
    cudaMemsetAsync((char*)p_hl, 0, 64 * 512 * sizeof(bf16));
    cudaMemsetAsync(p_barc, 0, 4 * 32 * sizeof(unsigned));

    const int KBIG = 1 << 30;

    // 0) operand prep (fp16)
    cvt_k<<<512, 256>>>(X, X16, (64L * 512 * 512) / 4);
    cvt_k<<<64, 256>>>(Wih, Wih16, (1536L * 512) / 4);
    cvt_k<<<64, 256>>>(Wao, Wao16, (512L * 1024) / 4);
    cvt_k<<<32, 256>>>(Wd, Wd16, (512L * 512) / 4);
    encprep_k<<<dim3(16, 16, 64), dim3(32, 8)>>>(Enc, E16, T16);

    // 1) xi = X @ Wih^T + bih : [32768,1536] fp32
    tgemm_16<1, 0><<<dim3(12, 256, 1), 256, TGB_SMEM>>>(
        X16, X16, KBIG, 512, Wih16, 512, bih,
        xi, nullptr, 1536, 512, 0, 0, 0);

    // 2) GRU scan -> dec fp16, h_last in g_hbh/g_hbl[0]
    gru_scan<<<128, 256, GRU_SMEM_BYTES>>>(Whh, bhh);

    // 3) scores[b] = dec[b] @ enc[b]^T : fp32
    tgemm_16<0, 0><<<dim3(4, 4, 64), 256, TGB_SMEM>>>(
        D16, D16, KBIG, 512, E16, 512, nullptr,
        sc, nullptr, 512, 512, 262144L, 262144L, 262144L);

    // 4) softmax (mask) -> attn fp16
    softmax_k<<<64 * 512, 256>>>(sc, Mask);

    // 5) mix[b] = attn[b] @ encT[b]^T : fp16 out
    tgemm_16<0, 1><<<dim3(4, 4, 64), 256, TGB_SMEM>>>(
        At16, At16, KBIG, 512, T16, 512, nullptr,
        nullptr, M16, 512, 512, 262144L, 262144L, 262144L);

    // 6) o1 = tanh(concat(mix, dec) @ Wao^T + bao) : fp16 out, K=1024
    tgemm_16<2, 1><<<dim3(4, 256, 1), 256, TGB_SMEM>>>(
        M16, D16, 512, 512, Wao16, 1024, bao,
        nullptr, O16, 512, 1024, 0, 0, 0);

    // 7) final = o1 @ Wd^T + bd -> d_out fp32
    tgemm_16<1, 0><<<dim3(4, 256, 1), 256, TGB_SMEM>>>(
        O16, O16, KBIG, 512, Wd16, 512, bd,
        out, nullptr, 512, 512, 0, 0, 0);

    // 8) h_last -> tail of d_out
    copy_h_k<<<128, 256>>>(out + (long)out_size - 64 * 512);
}